// round 3
// baseline (speedup 1.0000x reference)
#include <cuda_runtime.h>

#define NN 20000
#define BB 64
#define EE 1280000
#define NBLK 313   // ceil(NN/64)

// Scratch (allocation-free per rules). __device__ globals are zero-initialized
// at load; g_count's zero-state is restored by scan_kernel every launch.
__device__ __align__(16) float g_xT[NN * BB];   // xT[n*64 + b]
__device__ int  g_count[NN];
__device__ int  g_off[NN + 1];
__device__ int  g_cursor[NN];
__device__ __align__(16) int2 g_edge[EE];       // dst-sorted (src, val) pairs

// K1: smem-tiled transpose x[B,N] -> xT[N,B]  +  dst histogram.
__global__ void prep_kernel(const float* __restrict__ x,
                            const int* __restrict__ dst) {
    __shared__ float t[64][65];
    int tid = threadIdx.x;
    int n0 = blockIdx.x * 64;

    // coalesced read: consecutive tid vary n within a b-row
    for (int i = tid; i < 64 * 64; i += 256) {
        int b = i >> 6, nc = i & 63;
        int n = n0 + nc;
        if (n < NN) t[nc][b] = x[b * NN + n];
    }
    __syncthreads();
    // coalesced write: consecutive tid vary b within an n-row
    for (int i = tid; i < 64 * 64; i += 256) {
        int nc = i >> 6, b = i & 63;
        int n = n0 + nc;
        if (n < NN) g_xT[n * 64 + b] = t[nc][b];
    }
    // histogram over this block's edge slice (requires g_count == 0 on entry;
    // invariant maintained by scan_kernel)
    int e0 = blockIdx.x * 4096;
    for (int i = tid; i < 4096; i += 256) {
        int e = e0 + i;
        if (e < EE) atomicAdd(&g_count[dst[e]], 1);
    }
}

// K2: single-block exclusive scan of g_count -> g_off / g_cursor.
// Also zeroes g_count (restores invariant for next graph replay).
__global__ void scan_kernel() {
    const int PER = 20;                 // 1024*20 = 20480 >= NN
    __shared__ int wsum[32];
    int tid = threadIdx.x, lane = tid & 31, wid = tid >> 5;
    int base = tid * PER;
    int local[PER];
    int sum = 0;
    #pragma unroll
    for (int i = 0; i < PER; i++) {
        int idx = base + i;
        int c = (idx < NN) ? g_count[idx] : 0;
        local[i] = sum;                 // thread-local exclusive prefix
        sum += c;
    }
    int v = sum;                        // warp inclusive scan of thread sums
    #pragma unroll
    for (int o = 1; o < 32; o <<= 1) {
        int nv = __shfl_up_sync(0xffffffffu, v, o);
        if (lane >= o) v += nv;
    }
    if (lane == 31) wsum[wid] = v;
    __syncthreads();
    if (wid == 0) {
        int s = wsum[lane];
        #pragma unroll
        for (int o = 1; o < 32; o <<= 1) {
            int ns = __shfl_up_sync(0xffffffffu, s, o);
            if (lane >= o) s += ns;
        }
        wsum[lane] = s;
    }
    __syncthreads();
    int thread_excl = ((wid > 0) ? wsum[wid - 1] : 0) + (v - sum);
    #pragma unroll
    for (int i = 0; i < PER; i++) {
        int idx = base + i;
        if (idx < NN) {
            int o = thread_excl + local[i];
            g_off[idx]    = o;
            g_cursor[idx] = o;
            g_count[idx]  = 0;          // restore zero-invariant
        }
    }
    if (tid == 0) g_off[NN] = EE;
}

// K3: bin edges into dst-sorted order (one 8B pair per edge).
__global__ void bin_kernel(const float* __restrict__ adj,
                           const float* __restrict__ w,
                           const int* __restrict__ src,
                           const int* __restrict__ dst) {
    int e = blockIdx.x * blockDim.x + threadIdx.x;
    if (e >= EE) return;
    int   d = dst[e];
    int   s = src[e];
    float v = adj[e] * w[e];
    int pos = atomicAdd(&g_cursor[d], 1);
    g_edge[pos] = make_int2(s, __float_as_int(v));
}

// K4: CSR SpMM (warp-per-node, register accumulation, NO float atomics)
// fused with the epilogue via an smem tile transpose.
__global__ void __launch_bounds__(512)
spmm_kernel(const float* __restrict__ x,
            const float* __restrict__ self_w,
            const float* __restrict__ bias,
            float* __restrict__ out) {
    __shared__ float tile[64][65];
    int tid = threadIdx.x, lane = tid & 31, wid = tid >> 5;  // 16 warps
    int n0 = blockIdx.x * 64;
    const float2* xT2 = (const float2*)g_xT;

    #pragma unroll 1
    for (int j = 0; j < 4; j++) {
        int nl = wid + j * 16;
        int n  = n0 + nl;
        if (n < NN) {
            int beg = g_off[n], end = g_off[n + 1];
            float2 acc = make_float2(0.f, 0.f);
            for (int base = beg; base < end; base += 32) {
                int idx = base + lane;
                int2 pr = (idx < end) ? g_edge[idx] : make_int2(0, 0);
                int cnt = min(32, end - base);
                if (cnt == 32) {
                    #pragma unroll
                    for (int k = 0; k < 32; k++) {
                        int   s = __shfl_sync(0xffffffffu, pr.x, k);
                        float v = __int_as_float(__shfl_sync(0xffffffffu, pr.y, k));
                        float2 xv = xT2[s * 32 + lane];   // 256B coalesced, L2-hit
                        acc.x = fmaf(v, xv.x, acc.x);
                        acc.y = fmaf(v, xv.y, acc.y);
                    }
                } else {
                    for (int k = 0; k < cnt; k++) {
                        int   s = __shfl_sync(0xffffffffu, pr.x, k);
                        float v = __int_as_float(__shfl_sync(0xffffffffu, pr.y, k));
                        float2 xv = xT2[s * 32 + lane];
                        acc.x = fmaf(v, xv.x, acc.x);
                        acc.y = fmaf(v, xv.y, acc.y);
                    }
                }
            }
            tile[nl][2 * lane]     = acc.x;
            tile[nl][2 * lane + 1] = acc.y;
        }
    }
    __syncthreads();
    // epilogue: coalesced writes to out[b*N + n]
    for (int i = tid; i < 64 * 64; i += 512) {
        int b = i >> 6, nl = i & 63;
        int n = n0 + nl;
        if (n < NN) {
            float sl = x[n] * self_w[n];   // x[0, n] — faithful reference quirk
            float vv = fmaf(tile[nl][b], sl, bias[n]);
            out[b * NN + n] = fmaxf(vv, 0.f);
        }
    }
}

extern "C" void kernel_launch(void* const* d_in, const int* in_sizes, int n_in,
                              void* d_out, int out_size) {
    const float* x      = (const float*)d_in[0];
    const float* adj    = (const float*)d_in[1];
    const float* w      = (const float*)d_in[2];
    const float* self_w = (const float*)d_in[3];
    const float* bias   = (const float*)d_in[4];
    const int*   src    = (const int*)d_in[5];
    const int*   dst    = (const int*)d_in[6];
    float* out = (float*)d_out;

    prep_kernel<<<NBLK, 256>>>(x, dst);
    scan_kernel<<<1, 1024>>>();
    bin_kernel<<<(EE + 255) / 256, 256>>>(adj, w, src, dst);
    spmm_kernel<<<NBLK, 512>>>(x, self_w, bias, out);
}

// round 5
// speedup vs baseline: 2.3950x; 2.3950x over previous
#include <cuda_runtime.h>

#define NN 20000
#define BB 64
#define EE 1280000
#define NBLK 313   // ceil(NN/64)

// Scratch (allocation-free per rules).
__device__ __align__(16) float g_xT[NN * BB];    // xT[n*64 + b]
__device__ __align__(16) float g_accT[NN * BB];  // accT[n*64 + b]

// K1: smem-tiled transpose x[B,N] -> xT[N,B] with float4 global reads and
// writes, plus float4 zeroing of the accumulator slice this block owns.
__global__ void __launch_bounds__(256)
prep_kernel(const float* __restrict__ x) {
    __shared__ float t[64][65];
    int tid = threadIdx.x;
    int n0 = blockIdx.x * 64;          // NN % 64 != 0; last block partial (n0=19968, 32 cols)
    int ncols = min(64, NN - n0);

    const float4* x4 = (const float4*)x;

    // Phase A: coalesced float4 reads along n. idx = b*16 + q covers 64 b x 16 q.
    for (int i = tid; i < 64 * 16; i += 256) {
        int b = i >> 4, q = i & 15;
        int nc = 4 * q;                // n-offset within tile
        if (nc < ncols) {
            float4 v = x4[b * (NN / 4) + (n0 >> 2) + q];
            t[nc + 0][b] = v.x;
            t[nc + 1][b] = v.y;
            t[nc + 2][b] = v.z;
            t[nc + 3][b] = v.w;
        }
    }
    __syncthreads();

    // Phase B: coalesced float4 writes along b into xT, and zero accT.
    float4* xT4  = (float4*)g_xT;
    float4* acc4 = (float4*)g_accT;
    const float4 z = make_float4(0.f, 0.f, 0.f, 0.f);
    for (int i = tid; i < 64 * 16; i += 256) {
        int nc = i >> 4, bq = i & 15;
        if (nc < ncols) {
            int n = n0 + nc;
            float4 v;
            v.x = t[nc][4 * bq + 0];
            v.y = t[nc][4 * bq + 1];
            v.z = t[nc][4 * bq + 2];
            v.w = t[nc][4 * bq + 3];
            xT4[n * 16 + bq]  = v;
            acc4[n * 16 + bq] = z;
        }
    }
}

// K2: edge scatter, half-warp per edge (unchanged from R2 — at LTS cap).
// Per edge: one LDG.128 gather from L2-resident xT + one red.global.add.v4.f32.
__global__ void scatter_kernel(const float* __restrict__ adj,
                               const float* __restrict__ w,
                               const int* __restrict__ src,
                               const int* __restrict__ dst) {
    int g = (blockIdx.x * blockDim.x + threadIdx.x) >> 5;  // warp id
    int lane = threadIdx.x & 31;
    int e = g * 32 + lane;
    if (e >= EE) return;  // EE % 32 == 0: whole warp exits together

    int   s = src[e];
    int   d = dst[e];
    float v = adj[e] * w[e];

    int half = lane >> 4;
    int ll   = lane & 15;

    const float4* xT4 = (const float4*)g_xT;

    #pragma unroll 1
    for (int j = 0; j < 16; j++) {
        int sel = 2 * j + half;
        int   sj = __shfl_sync(0xffffffffu, s, sel);
        int   dj = __shfl_sync(0xffffffffu, d, sel);
        float vj = __shfl_sync(0xffffffffu, v, sel);

        float4 xv = xT4[sj * 16 + ll];           // LDG.128, coalesced, L2-hit
        float4 r;
        r.x = vj * xv.x;  r.y = vj * xv.y;
        r.z = vj * xv.z;  r.w = vj * xv.w;

        float* accp = &g_accT[dj * 64 + 4 * ll]; // 16B-aligned
        asm volatile("red.global.add.v4.f32 [%0], {%1, %2, %3, %4};"
                     :: "l"(accp), "f"(r.x), "f"(r.y), "f"(r.z), "f"(r.w)
                     : "memory");
    }
}

// K3: epilogue. Tile-transpose accT [N,B] -> out [B,N] with float4 global
// reads and writes; out = relu(acc * (x[0,n]*self_w[n]) + bias[n]).
__global__ void __launch_bounds__(256)
epilogue_kernel(const float* __restrict__ x,
                const float* __restrict__ self_w,
                const float* __restrict__ bias,
                float* __restrict__ out) {
    __shared__ float tile[64][65];
    __shared__ float s_sl[64];
    __shared__ float s_b[64];
    int tid = threadIdx.x;
    int n0 = blockIdx.x * 64;
    int ncols = min(64, NN - n0);

    // Load accT rows (float4 along b) + per-n scalars.
    const float4* acc4 = (const float4*)g_accT;
    for (int i = tid; i < 64 * 16; i += 256) {
        int nc = i >> 4, bq = i & 15;
        if (nc < ncols) {
            int n = n0 + nc;
            float4 v = acc4[n * 16 + bq];
            tile[nc][4 * bq + 0] = v.x;
            tile[nc][4 * bq + 1] = v.y;
            tile[nc][4 * bq + 2] = v.z;
            tile[nc][4 * bq + 3] = v.w;
        }
    }
    if (tid < 64) {
        int n = n0 + tid;
        if (tid < ncols) {
            s_sl[tid] = x[n] * self_w[n];   // x[0, n] — faithful reference quirk
            s_b[tid]  = bias[n];
        }
    }
    __syncthreads();

    // Store phase: float4 writes along n into out[b*NN + n].
    float4* out4 = (float4*)out;
    for (int i = tid; i < 64 * 16; i += 256) {
        int b = i >> 4, q = i & 15;
        int nc = 4 * q;
        if (nc < ncols) {
            float4 r;
            r.x = fmaxf(fmaf(tile[nc + 0][b], s_sl[nc + 0], s_b[nc + 0]), 0.f);
            r.y = fmaxf(fmaf(tile[nc + 1][b], s_sl[nc + 1], s_b[nc + 1]), 0.f);
            r.z = fmaxf(fmaf(tile[nc + 2][b], s_sl[nc + 2], s_b[nc + 2]), 0.f);
            r.w = fmaxf(fmaf(tile[nc + 3][b], s_sl[nc + 3], s_b[nc + 3]), 0.f);
            out4[b * (NN / 4) + (n0 >> 2) + q] = r;
        }
    }
}

extern "C" void kernel_launch(void* const* d_in, const int* in_sizes, int n_in,
                              void* d_out, int out_size) {
    const float* x      = (const float*)d_in[0];
    const float* adj    = (const float*)d_in[1];
    const float* w      = (const float*)d_in[2];
    const float* self_w = (const float*)d_in[3];
    const float* bias   = (const float*)d_in[4];
    const int*   src    = (const int*)d_in[5];
    const int*   dst    = (const int*)d_in[6];
    float* out = (float*)d_out;

    prep_kernel<<<NBLK, 256>>>(x);
    scatter_kernel<<<EE / 256, 256>>>(adj, w, src, dst);
    epilogue_kernel<<<NBLK, 256>>>(x, self_w, bias, out);
}